// round 4
// baseline (speedup 1.0000x reference)
#include <cuda_runtime.h>
#include <cuda_bf16.h>
#include <cstdint>

#define CUBE_L   512
#define EQU_H    1024
#define EQU_W    2048
#define E_COUNT  4
#define CHANNELS 3
#define PLANE    (CUBE_L * CUBE_L)      // 262144
#define NPIX     (EQU_H * EQU_W)        // 2097152
#define PXT      4                      // pixels per thread

// Each thread handles 4 consecutive pixels along w.
// Per plane (e,c): 16 gather loads (compiler-scheduled for MLP),
// 4 bilinear blends, one STG.128.
__global__ __launch_bounds__(128) void cube2equirec_kernel(
    const float* __restrict__ x,        // (E*6, C, L, L)
    const float* __restrict__ uv,       // (H, W, 2)
    const int*   __restrict__ face_idx, // (H, W)
    float*       __restrict__ out)      // (E, C, H, W)
{
    const int t = blockIdx.x * blockDim.x + threadIdx.x;
    const int p0 = t * PXT;
    if (p0 >= NPIX) return;

    // LUT loads: uv for 4 px = 8 floats = 2x float4; face = int4
    const float4 uva = __ldcs(reinterpret_cast<const float4*>(uv) + 2 * t);
    const float4 uvb = __ldcs(reinterpret_cast<const float4*>(uv) + 2 * t + 1);
    const int4  f4  = __ldcs(reinterpret_cast<const int4*>(face_idx) + t);

    float u[PXT], v[PXT];
    u[0] = uva.x; v[0] = uva.y;
    u[1] = uva.z; v[1] = uva.w;
    u[2] = uvb.x; v[2] = uvb.y;
    u[3] = uvb.z; v[3] = uvb.w;
    const int f[PXT] = { f4.x, f4.y, f4.z, f4.w };

    // Per-pixel tap offsets (include face base: plane index = 18e + 3f + c)
    int  toff[PXT][4];
    float w00[PXT], w01[PXT], w10[PXT], w11[PXT];
    #pragma unroll
    for (int j = 0; j < PXT; ++j) {
        int x0 = (int)floorf(u[j]);
        int y0 = (int)floorf(v[j]);
        x0 = min(max(x0, 0), CUBE_L - 1);
        y0 = min(max(y0, 0), CUBE_L - 1);
        const int x1 = min(x0 + 1, CUBE_L - 1);
        const int y1 = min(y0 + 1, CUBE_L - 1);
        const float wx = u[j] - (float)x0;
        const float wy = v[j] - (float)y0;
        w00[j] = (1.0f - wx) * (1.0f - wy);
        w01[j] = wx * (1.0f - wy);
        w10[j] = (1.0f - wx) * wy;
        w11[j] = wx * wy;
        const int fb = 3 * f[j] * PLANE;
        toff[j][0] = fb + y0 * CUBE_L + x0;
        toff[j][1] = fb + y0 * CUBE_L + x1;
        toff[j][2] = fb + y1 * CUBE_L + x0;
        toff[j][3] = fb + y1 * CUBE_L + x1;
    }

    // 12 planes: gather 16 taps, blend 4 px, one 128-bit streaming store.
    #pragma unroll
    for (int e = 0; e < E_COUNT; ++e) {
        #pragma unroll
        for (int c = 0; c < CHANNELS; ++c) {
            const float* __restrict__ pb = x + (size_t)(18 * e + c) * PLANE;
            float g[PXT][4];
            #pragma unroll
            for (int j = 0; j < PXT; ++j) {
                g[j][0] = __ldg(pb + toff[j][0]);
                g[j][1] = __ldg(pb + toff[j][1]);
                g[j][2] = __ldg(pb + toff[j][2]);
                g[j][3] = __ldg(pb + toff[j][3]);
            }
            float4 r;
            r.x = g[0][0]*w00[0] + g[0][1]*w01[0] + g[0][2]*w10[0] + g[0][3]*w11[0];
            r.y = g[1][0]*w00[1] + g[1][1]*w01[1] + g[1][2]*w10[1] + g[1][3]*w11[1];
            r.z = g[2][0]*w00[2] + g[2][1]*w01[2] + g[2][2]*w10[2] + g[2][3]*w11[2];
            r.w = g[3][0]*w00[3] + g[3][1]*w01[3] + g[3][2]*w10[3] + g[3][3]*w11[3];
            const int k = e * CHANNELS + c;
            __stcs(reinterpret_cast<float4*>(out + (size_t)k * NPIX) + t, r);
        }
    }
}

extern "C" void kernel_launch(void* const* d_in, const int* in_sizes, int n_in,
                              void* d_out, int out_size)
{
    const float* x        = (const float*)d_in[0];
    const float* uv       = (const float*)d_in[1];
    const int*   face_idx = (const int*)d_in[2];
    float*       out      = (float*)d_out;

    const int nthreads_total = NPIX / PXT;   // 524288
    const int threads = 128;
    const int blocks = nthreads_total / threads;  // 4096
    cube2equirec_kernel<<<blocks, threads>>>(x, uv, face_idx, out);
}

// round 5
// speedup vs baseline: 1.4900x; 1.4900x over previous
#include <cuda_runtime.h>
#include <cuda_bf16.h>
#include <cstdint>

#define CUBE_L   512
#define EQU_H    1024
#define EQU_W    2048
#define E_COUNT  4
#define CHANNELS 3
#define PLANE    (CUBE_L * CUBE_L)      // 262144
#define NPIX     (EQU_H * EQU_W)        // 2097152

#define TILE_W   32
#define TILE_H   16

// 2D-tiled mapping: each 512-thread block covers a 32(w) x 16(h) equirect
// tile. Each warp is 32 consecutive pixels along w (max intra-warp gather
// coherence); the 16 rows of the tile share cube-face tap rows inside one
// SM's L1 (vertical bilinear windows overlap ~50% between adjacent rows).
__global__ __launch_bounds__(TILE_W * TILE_H) void cube2equirec_kernel(
    const float* __restrict__ x,        // (E*6, C, L, L)
    const float* __restrict__ uv,       // (H, W, 2)
    const int*   __restrict__ face_idx, // (H, W)
    float*       __restrict__ out)      // (E, C, H, W)
{
    const int w = blockIdx.x * TILE_W + (threadIdx.x & (TILE_W - 1));
    const int h = blockIdx.y * TILE_H + (threadIdx.x >> 5);
    const int p = h * EQU_W + w;

    // LUT loads (read exactly once per pixel across whole kernel)
    const float2 uvp = __ldcs(reinterpret_cast<const float2*>(uv) + p);
    const int f = __ldcs(face_idx + p);

    const float u = uvp.x;
    const float v = uvp.y;

    int x0 = (int)floorf(u);
    int y0 = (int)floorf(v);
    x0 = min(max(x0, 0), CUBE_L - 1);
    y0 = min(max(y0, 0), CUBE_L - 1);
    const int x1 = min(x0 + 1, CUBE_L - 1);
    const int y1 = min(y0 + 1, CUBE_L - 1);

    const float wx = u - (float)x0;
    const float wy = v - (float)y0;
    const float w00 = (1.0f - wx) * (1.0f - wy);
    const float w01 = wx * (1.0f - wy);
    const float w10 = (1.0f - wx) * wy;
    const float w11 = wx * wy;

    const int o00 = y0 * CUBE_L + x0;
    const int o01 = y0 * CUBE_L + x1;
    const int o10 = y1 * CUBE_L + x0;
    const int o11 = y1 * CUBE_L + x1;

    #pragma unroll
    for (int e = 0; e < E_COUNT; ++e) {
        const float* __restrict__ face_base =
            x + (size_t)((e * 6 + f) * CHANNELS) * PLANE;
        #pragma unroll
        for (int c = 0; c < CHANNELS; ++c) {
            const float* __restrict__ b = face_base + (size_t)c * PLANE;
            const float g00 = __ldg(b + o00);
            const float g01 = __ldg(b + o01);
            const float g10 = __ldg(b + o10);
            const float g11 = __ldg(b + o11);
            const float val = g00 * w00 + g01 * w01 + g10 * w10 + g11 * w11;
            __stcs(out + (size_t)(e * CHANNELS + c) * NPIX + p, val);
        }
    }
}

extern "C" void kernel_launch(void* const* d_in, const int* in_sizes, int n_in,
                              void* d_out, int out_size)
{
    const float* x        = (const float*)d_in[0];
    const float* uv       = (const float*)d_in[1];
    const int*   face_idx = (const int*)d_in[2];
    float*       out      = (float*)d_out;

    dim3 block(TILE_W * TILE_H);                      // 512 threads
    dim3 grid(EQU_W / TILE_W, EQU_H / TILE_H);        // 64 x 64
    cube2equirec_kernel<<<grid, block>>>(x, uv, face_idx, out);
}